// round 3
// baseline (speedup 1.0000x reference)
#include <cuda_runtime.h>
#include <cstdint>

// Problem dims (fixed by the dataset)
#define B_DIM 8192
#define DIN   1024
#define H_DIM 2048

// Tiling
#define BM 128
#define BN 256
#define BK 32           // 32 fp32 = 128B rows (swizzle atom)
#define NK 96           // 3072 / 32 total K-chunks (x|u concat)
#define NKX 32          // first 32 chunks: x / win (K=1024)
#define STAGES 3
#define NTHREADS 256

#define A_BYTES (BM * BK * 4)              // 16 KB
#define B_BYTES (BN * BK * 4)              // 32 KB
#define STAGE_BYTES (A_BYTES + B_BYTES)    // 48 KB
#define SMEM_TOTAL (STAGES * STAGE_BYTES)  // 144 KB

__device__ __forceinline__ uint32_t smem_u32(const void* p) {
    uint32_t a;
    asm("{ .reg .u64 t; cvta.to.shared.u64 t, %1; cvt.u32.u64 %0, t; }"
        : "=r"(a) : "l"(p));
    return a;
}

__device__ __forceinline__ void cp_async16(uint32_t saddr, const float* g) {
    asm volatile("cp.async.cg.shared.global [%0], [%1], 16;\n"
                 :: "r"(saddr), "l"(g));
}

__device__ __forceinline__ void cp_commit() {
    asm volatile("cp.async.commit_group;\n" ::: "memory");
}

template <int N>
__device__ __forceinline__ void cp_wait() {
    asm volatile("cp.async.wait_group %0;\n" :: "n"(N) : "memory");
}

__device__ __forceinline__ float lds32(uint32_t addr) {
    float v;
    asm volatile("ld.shared.f32 %0, [%1];" : "=f"(v) : "r"(addr));
    return v;
}

// mma.sync m16n8k8 TF32 (raw fp32 bits truncated to tf32 by HW)
__device__ __forceinline__ void mma_tf32(float& c0, float& c1, float& c2, float& c3,
                                         float a0, float a1, float a2, float a3,
                                         float b0, float b1) {
    asm volatile(
        "mma.sync.aligned.m16n8k8.row.col.f32.tf32.tf32.f32 "
        "{%0,%1,%2,%3}, {%4,%5,%6,%7}, {%8,%9}, {%0,%1,%2,%3};"
        : "+f"(c0), "+f"(c1), "+f"(c2), "+f"(c3)
        : "r"(__float_as_uint(a0)), "r"(__float_as_uint(a1)),
          "r"(__float_as_uint(a2)), "r"(__float_as_uint(a3)),
          "r"(__float_as_uint(b0)), "r"(__float_as_uint(b1)));
}

__global__ void __launch_bounds__(NTHREADS, 1)
sfa_rnn_kernel(const float* __restrict__ x,
               const float* __restrict__ u,
               const float* __restrict__ v,
               const float* __restrict__ win,
               const float* __restrict__ wr,
               const float* __restrict__ bias,
               float* __restrict__ out) {
    extern __shared__ char smem[];
    const uint32_t sbase = smem_u32(smem);

    const int tid  = threadIdx.x;
    const int wid  = tid >> 5;
    const int lane = tid & 31;
    const int lq   = lane >> 2;  // 0..7  (groupID)
    const int lr   = lane & 3;   // 0..3  (threadID in group)
    const int wm   = wid & 1;    // M half (64 rows)
    const int wn   = wid >> 1;   // N quarter (64 cols)

    const int nb = blockIdx.x * BN;
    const int mb = blockIdx.y * BM;

    // ---------------- producer geometry ----------------
    const int rbase = tid >> 3;  // 0..31
    const int c16   = tid & 7;   // 16B chunk within 128B row
    const uint32_t swbase =
        (uint32_t)rbase * 128u + ((uint32_t)(c16 ^ (rbase & 7)) << 4);

    const float* gax = x   + (size_t)(mb + rbase) * DIN   + c16 * 4;
    const float* gau = u   + (size_t)(mb + rbase) * H_DIM + c16 * 4;
    const float* gbw = win + (size_t)(nb + rbase) * DIN   + c16 * 4;
    const float* gbr = wr  + (size_t)(nb + rbase) * H_DIM + c16 * 4;

    auto issue_chunk = [&](int k) {
        const int s = k % STAGES;
        const uint32_t sA = sbase + s * STAGE_BYTES;
        const uint32_t sB = sA + A_BYTES;
        if (k < NKX) {
            const float* ga = gax + k * BK;
            const float* gb = gbw + k * BK;
#pragma unroll
            for (int i = 0; i < 4; i++)
                cp_async16(sA + swbase + i * 4096u, ga + (size_t)i * 32 * DIN);
#pragma unroll
            for (int i = 0; i < 8; i++)
                cp_async16(sB + swbase + i * 4096u, gb + (size_t)i * 32 * DIN);
        } else {
            const float* ga = gau + (k - NKX) * BK;
            const float* gb = gbr + (k - NKX) * BK;
#pragma unroll
            for (int i = 0; i < 4; i++)
                cp_async16(sA + swbase + i * 4096u, ga + (size_t)i * 32 * H_DIM);
#pragma unroll
            for (int i = 0; i < 8; i++)
                cp_async16(sB + swbase + i * 4096u, gb + (size_t)i * 32 * H_DIM);
        }
    };

    // ---------------- consumer geometry ----------------
    // A fragment (m16n8k8 tf32): a0=(lq, lr), a1=(lq+8, lr),
    //                            a2=(lq, lr+4), a3=(lq+8, lr+4)
    // Element (row, kcol) lives at row*128 + ((kcol>>2) ^ (row&7))*16 + (kcol&3)*4
    uint32_t baseA[4][2];
#pragma unroll
    for (int mi = 0; mi < 4; mi++) {
#pragma unroll
        for (int h = 0; h < 2; h++) {
            const uint32_t row = (uint32_t)(wm * 64 + mi * 16 + lq + 8 * h);
            baseA[mi][h] = row * 128u + (uint32_t)lr * 4u;
        }
    }
    // B fragment: b0=(k=lr, n=lq), b1=(k=lr+4, n=lq); SMEM row = n, col = k.
    uint32_t baseB[8];
#pragma unroll
    for (int ni = 0; ni < 8; ni++) {
        const uint32_t row = (uint32_t)(wn * 64 + ni * 8 + lq);
        baseB[ni] = row * 128u + (uint32_t)lr * 4u;
    }
    const uint32_t xorv = (uint32_t)lq;  // (row & 7) for all fragment rows

    float acc[4][8][4];
#pragma unroll
    for (int mi = 0; mi < 4; mi++)
#pragma unroll
        for (int ni = 0; ni < 8; ni++)
#pragma unroll
            for (int r = 0; r < 4; r++) acc[mi][ni][r] = 0.0f;

    // ---------------- prologue ----------------
    issue_chunk(0); cp_commit();
    issue_chunk(1); cp_commit();

    // ---------------- mainloop ----------------
#pragma unroll 1
    for (int k = 0; k < NK; k++) {
        if (k + STAGES - 1 < NK) issue_chunk(k + STAGES - 1);
        cp_commit();
        cp_wait<2>();
        __syncthreads();

        const int s = k % STAGES;
        const uint32_t sA = sbase + s * STAGE_BYTES;
        const uint32_t sB = sA + A_BYTES;

#pragma unroll
        for (int ks = 0; ks < 4; ks++) {
            const uint32_t sw0 = (((uint32_t)(ks * 2 + 0)) ^ xorv) << 4;
            const uint32_t sw1 = (((uint32_t)(ks * 2 + 1)) ^ xorv) << 4;

            float a[4][4];
#pragma unroll
            for (int mi = 0; mi < 4; mi++) {
                a[mi][0] = lds32(sA + baseA[mi][0] + sw0);  // (lq,   k=lr)
                a[mi][1] = lds32(sA + baseA[mi][1] + sw0);  // (lq+8, k=lr)
                a[mi][2] = lds32(sA + baseA[mi][0] + sw1);  // (lq,   k=lr+4)
                a[mi][3] = lds32(sA + baseA[mi][1] + sw1);  // (lq+8, k=lr+4)
            }
            float b[8][2];
#pragma unroll
            for (int ni = 0; ni < 8; ni++) {
                b[ni][0] = lds32(sB + baseB[ni] + sw0);
                b[ni][1] = lds32(sB + baseB[ni] + sw1);
            }
#pragma unroll
            for (int mi = 0; mi < 4; mi++)
#pragma unroll
                for (int ni = 0; ni < 8; ni++)
                    mma_tf32(acc[mi][ni][0], acc[mi][ni][1],
                             acc[mi][ni][2], acc[mi][ni][3],
                             a[mi][0], a[mi][1], a[mi][2], a[mi][3],
                             b[ni][0], b[ni][1]);
        }
        __syncthreads();
    }

    // ---------------- fused epilogue ----------------
    const float cu  = 1.0f - (1.0f / 10.0f);
    const float au  = 1.0f / 10.0f;
    const float cv  = 1.0f - (1.0f / 150.0f);
    const float cvm = 10.0f / 150.0f;
    const size_t OUTV = (size_t)B_DIM * H_DIM;

#pragma unroll
    for (int mi = 0; mi < 4; mi++) {
#pragma unroll
        for (int ni = 0; ni < 8; ni++) {
            const int r0 = mb + wm * 64 + mi * 16 + lq;
            const int c  = nb + wn * 64 + ni * 8 + lr * 2;
            const float2 bn = *reinterpret_cast<const float2*>(bias + c);
#pragma unroll
            for (int h = 0; h < 2; h++) {
                const size_t off = (size_t)(r0 + 8 * h) * H_DIM + c;
                const float2 uu = *reinterpret_cast<const float2*>(u + off);
                const float2 vv = *reinterpret_cast<const float2*>(v + off);
                const float g0 = acc[mi][ni][2 * h + 0];
                const float g1 = acc[mi][ni][2 * h + 1];
                const float vn0 = fmaxf(cv * vv.x + cvm * uu.x, 0.0f);
                const float vn1 = fmaxf(cv * vv.y + cvm * uu.y, 0.0f);
                const float un0 = fmaxf(cu * uu.x + au * (g0 + bn.x - vn0), 0.0f);
                const float un1 = fmaxf(cu * uu.y + au * (g1 + bn.y - vn1), 0.0f);
                *reinterpret_cast<float2*>(out + off)        = make_float2(un0, un1);
                *reinterpret_cast<float2*>(out + OUTV + off) = make_float2(vn0, vn1);
            }
        }
    }
}

extern "C" void kernel_launch(void* const* d_in, const int* in_sizes, int n_in,
                              void* d_out, int out_size) {
    (void)in_sizes; (void)n_in; (void)out_size;
    const float* x    = (const float*)d_in[0];
    const float* u    = (const float*)d_in[1];
    const float* v    = (const float*)d_in[2];
    const float* win  = (const float*)d_in[3];
    const float* wr   = (const float*)d_in[4];
    const float* bias = (const float*)d_in[5];
    float* out = (float*)d_out;

    cudaFuncSetAttribute(sfa_rnn_kernel,
                         cudaFuncAttributeMaxDynamicSharedMemorySize, SMEM_TOTAL);
    dim3 grid(H_DIM / BN, B_DIM / BM);  // (8, 64) = 512 CTAs
    sfa_rnn_kernel<<<grid, NTHREADS, SMEM_TOTAL>>>(x, u, v, win, wr, bias, out);
}

// round 4
// speedup vs baseline: 1.8410x; 1.8410x over previous
#include <cuda_runtime.h>
#include <cuda_bf16.h>
#include <cstdint>

// Problem dims (fixed by the dataset)
#define B_DIM 8192
#define DIN   1024
#define H_DIM 2048

// Tiling
#define BM 128
#define BN 256
#define BKE 64          // bf16 K-elements per chunk = 128B rows (swizzle atom)
#define NK 48           // 3072 / 64
#define NKX 16          // first 16 chunks: x / win (K=1024)
#define STAGES 3
#define NTHREADS 256

#define A_BYTES (BM * 128)                 // 16 KB
#define B_BYTES (BN * 128)                 // 32 KB
#define STAGE_BYTES (A_BYTES + B_BYTES)    // 48 KB
#define SMEM_TOTAL (STAGES * STAGE_BYTES)  // 144 KB

// bf16 copies of the inputs (static scratch; no allocation allowed)
__device__ __nv_bfloat16 g_xb[(size_t)B_DIM * DIN];
__device__ __nv_bfloat16 g_ub[(size_t)B_DIM * H_DIM];
__device__ __nv_bfloat16 g_winb[(size_t)H_DIM * DIN];
__device__ __nv_bfloat16 g_wrb[(size_t)H_DIM * H_DIM];

__device__ __forceinline__ uint32_t smem_u32(const void* p) {
    uint32_t a;
    asm("{ .reg .u64 t; cvta.to.shared.u64 t, %1; cvt.u32.u64 %0, t; }"
        : "=r"(a) : "l"(p));
    return a;
}

__device__ __forceinline__ void cp_async16(uint32_t saddr, const void* g) {
    asm volatile("cp.async.cg.shared.global [%0], [%1], 16;\n"
                 :: "r"(saddr), "l"(g));
}

__device__ __forceinline__ void cp_commit() {
    asm volatile("cp.async.commit_group;\n" ::: "memory");
}

template <int N>
__device__ __forceinline__ void cp_wait() {
    asm volatile("cp.async.wait_group %0;\n" :: "n"(N) : "memory");
}

#define LDSM_X4(r, addr) \
    asm volatile("ldmatrix.sync.aligned.m8n8.x4.shared.b16 {%0,%1,%2,%3}, [%4];" \
        : "=r"((r)[0]), "=r"((r)[1]), "=r"((r)[2]), "=r"((r)[3]) : "r"(addr))

__device__ __forceinline__ void mma_bf16(float* c, const uint32_t* a,
                                         uint32_t b0, uint32_t b1) {
    asm volatile(
        "mma.sync.aligned.m16n8k16.row.col.f32.bf16.bf16.f32 "
        "{%0,%1,%2,%3}, {%4,%5,%6,%7}, {%8,%9}, {%0,%1,%2,%3};"
        : "+f"(c[0]), "+f"(c[1]), "+f"(c[2]), "+f"(c[3])
        : "r"(a[0]), "r"(a[1]), "r"(a[2]), "r"(a[3]), "r"(b0), "r"(b1));
}

// ---------------------------------------------------------------------------
// fp32 -> bf16 conversion pre-pass (one float4 per thread)
// ---------------------------------------------------------------------------
#define SX4 ((size_t)B_DIM * DIN / 4)     // 2,097,152
#define SU4 ((size_t)B_DIM * H_DIM / 4)   // 4,194,304
#define SW4 ((size_t)H_DIM * DIN / 4)     //   524,288
#define SR4 ((size_t)H_DIM * H_DIM / 4)   // 1,048,576
#define TOTAL4 (SX4 + SU4 + SW4 + SR4)    // 7,864,320

__global__ void __launch_bounds__(256)
convert_kernel(const float4* __restrict__ x, const float4* __restrict__ u,
               const float4* __restrict__ win, const float4* __restrict__ wr) {
    const size_t i = (size_t)blockIdx.x * blockDim.x + threadIdx.x;
    float4 f;
    __nv_bfloat16* dst;
    size_t j;
    if (i < SX4)                   { j = i;                   f = x[j];   dst = g_xb;   }
    else if (i < SX4 + SU4)        { j = i - SX4;             f = u[j];   dst = g_ub;   }
    else if (i < SX4 + SU4 + SW4)  { j = i - SX4 - SU4;       f = win[j]; dst = g_winb; }
    else if (i < TOTAL4)           { j = i - SX4 - SU4 - SW4; f = wr[j];  dst = g_wrb;  }
    else return;
    __nv_bfloat162* o = reinterpret_cast<__nv_bfloat162*>(dst) + j * 2;
    o[0] = __floats2bfloat162_rn(f.x, f.y);
    o[1] = __floats2bfloat162_rn(f.z, f.w);
}

// ---------------------------------------------------------------------------
// Fused GEMM + SfaRNN epilogue
// ---------------------------------------------------------------------------
__global__ void __launch_bounds__(NTHREADS, 1)
sfa_rnn_kernel(const float* __restrict__ u,
               const float* __restrict__ v,
               const float* __restrict__ bias,
               float* __restrict__ out) {
    extern __shared__ char smem[];
    const uint32_t sbase = smem_u32(smem);

    const int tid  = threadIdx.x;
    const int wid  = tid >> 5;
    const int lane = tid & 31;
    const int lq   = lane >> 2;
    const int lr   = lane & 3;
    const int wm   = wid & 1;    // M half (64 rows)
    const int wn   = wid >> 1;   // N quarter (64 cols)

    const int nb = blockIdx.x * BN;
    const int mb = blockIdx.y * BM;

    // ---------------- producer geometry ----------------
    // Each thread: 4 x 16B chunks of A + 8 x 16B chunks of B per K-chunk.
    const int rbase = tid >> 3;  // 0..31
    const int c16   = tid & 7;   // 16B chunk within 128B row
    const uint32_t swbase =
        (uint32_t)rbase * 128u + ((uint32_t)(c16 ^ (rbase & 7)) << 4);

    const __nv_bfloat16* gax = g_xb   + (size_t)(mb + rbase) * DIN   + c16 * 8;
    const __nv_bfloat16* gau = g_ub   + (size_t)(mb + rbase) * H_DIM + c16 * 8;
    const __nv_bfloat16* gbw = g_winb + (size_t)(nb + rbase) * DIN   + c16 * 8;
    const __nv_bfloat16* gbr = g_wrb  + (size_t)(nb + rbase) * H_DIM + c16 * 8;

    auto issue_chunk = [&](int k) {
        const int s = k % STAGES;
        const uint32_t sA = sbase + s * STAGE_BYTES;
        const uint32_t sB = sA + A_BYTES;
        if (k < NKX) {
            const __nv_bfloat16* ga = gax + k * BKE;
            const __nv_bfloat16* gb = gbw + k * BKE;
#pragma unroll
            for (int i = 0; i < 4; i++)
                cp_async16(sA + swbase + i * 4096u, ga + (size_t)i * 32 * DIN);
#pragma unroll
            for (int i = 0; i < 8; i++)
                cp_async16(sB + swbase + i * 4096u, gb + (size_t)i * 32 * DIN);
        } else {
            const __nv_bfloat16* ga = gau + (k - NKX) * BKE;
            const __nv_bfloat16* gb = gbr + (k - NKX) * BKE;
#pragma unroll
            for (int i = 0; i < 4; i++)
                cp_async16(sA + swbase + i * 4096u, ga + (size_t)i * 32 * H_DIM);
#pragma unroll
            for (int i = 0; i < 8; i++)
                cp_async16(sB + swbase + i * 4096u, gb + (size_t)i * 32 * H_DIM);
        }
    };

    // ---------------- consumer geometry (ldmatrix) ----------------
    // A (m16n8k16): x4 matrices = (m0..7,kc), (m8..15,kc), (m0..7,kc+1), (m8..15,kc+1)
    //   lane -> mat = lane>>3, r = lane&7:
    //   row = m0 + (lane&7) + 8*((lane>>3)&1), chunk = 2ks + (lane>>4)
    // B (n-rows, k contiguous): x4 = (n0..7,kc), (n0..7,kc+1), (n8..15,kc), (n8..15,kc+1)
    //   row = n0 + (lane&7) + 8*(lane>>4), chunk = 2ks + ((lane>>3)&1)
    const uint32_t r8   = (uint32_t)(lane & 7);
    const uint32_t a_hi = (uint32_t)(lane >> 4);
    const uint32_t a_m8 = (uint32_t)(((lane >> 3) & 1) << 3);
    const uint32_t b_hi = (uint32_t)((lane >> 3) & 1);
    const uint32_t b_n8 = (uint32_t)((lane >> 4) << 3);

    uint32_t baseA[4];
#pragma unroll
    for (int mi = 0; mi < 4; mi++)
        baseA[mi] = (uint32_t)(wm * 64 + mi * 16) * 128u + (r8 + a_m8) * 128u;
    uint32_t baseB[4];
#pragma unroll
    for (int ni2 = 0; ni2 < 4; ni2++)
        baseB[ni2] = (uint32_t)(wn * 64 + ni2 * 16) * 128u + (r8 + b_n8) * 128u;

    float acc[4][8][4];
#pragma unroll
    for (int mi = 0; mi < 4; mi++)
#pragma unroll
        for (int ni = 0; ni < 8; ni++)
#pragma unroll
            for (int r = 0; r < 4; r++) acc[mi][ni][r] = 0.0f;

    // ---------------- prologue ----------------
    issue_chunk(0); cp_commit();
    issue_chunk(1); cp_commit();

    // ---------------- mainloop (single barrier per chunk) ----------------
#pragma unroll 1
    for (int k = 0; k < NK; k++) {
        cp_wait<1>();
        __syncthreads();
        if (k + 2 < NK) issue_chunk(k + 2);
        cp_commit();

        const int s = k % STAGES;
        const uint32_t sA = sbase + s * STAGE_BYTES;
        const uint32_t sB = sA + A_BYTES;

#pragma unroll
        for (int ks = 0; ks < 4; ks++) {
            const uint32_t offA = (((uint32_t)(2 * ks) + a_hi) ^ r8) << 4;
            const uint32_t offB = (((uint32_t)(2 * ks) + b_hi) ^ r8) << 4;

            uint32_t a[4][4];
#pragma unroll
            for (int mi = 0; mi < 4; mi++) LDSM_X4(a[mi], sA + baseA[mi] + offA);
            uint32_t b[4][4];
#pragma unroll
            for (int ni2 = 0; ni2 < 4; ni2++) LDSM_X4(b[ni2], sB + baseB[ni2] + offB);

#pragma unroll
            for (int mi = 0; mi < 4; mi++)
#pragma unroll
                for (int ni = 0; ni < 8; ni++)
                    mma_bf16(acc[mi][ni], a[mi],
                             b[ni >> 1][(ni & 1) * 2 + 0],
                             b[ni >> 1][(ni & 1) * 2 + 1]);
        }
    }

    // ---------------- fused epilogue ----------------
    const float cu  = 1.0f - (1.0f / 10.0f);
    const float au  = 1.0f / 10.0f;
    const float cv  = 1.0f - (1.0f / 150.0f);
    const float cvm = 10.0f / 150.0f;
    const size_t OUTV = (size_t)B_DIM * H_DIM;

#pragma unroll
    for (int mi = 0; mi < 4; mi++) {
#pragma unroll
        for (int ni = 0; ni < 8; ni++) {
            const int r0 = mb + wm * 64 + mi * 16 + lq;
            const int c  = nb + wn * 64 + ni * 8 + lr * 2;
            const float2 bn = *reinterpret_cast<const float2*>(bias + c);
#pragma unroll
            for (int h = 0; h < 2; h++) {
                const size_t off = (size_t)(r0 + 8 * h) * H_DIM + c;
                const float2 uu = *reinterpret_cast<const float2*>(u + off);
                const float2 vv = *reinterpret_cast<const float2*>(v + off);
                const float g0 = acc[mi][ni][2 * h + 0];
                const float g1 = acc[mi][ni][2 * h + 1];
                const float vn0 = fmaxf(cv * vv.x + cvm * uu.x, 0.0f);
                const float vn1 = fmaxf(cv * vv.y + cvm * uu.y, 0.0f);
                const float un0 = fmaxf(cu * uu.x + au * (g0 + bn.x - vn0), 0.0f);
                const float un1 = fmaxf(cu * uu.y + au * (g1 + bn.y - vn1), 0.0f);
                *reinterpret_cast<float2*>(out + off)        = make_float2(un0, un1);
                *reinterpret_cast<float2*>(out + OUTV + off) = make_float2(vn0, vn1);
            }
        }
    }
}

extern "C" void kernel_launch(void* const* d_in, const int* in_sizes, int n_in,
                              void* d_out, int out_size) {
    (void)in_sizes; (void)n_in; (void)out_size;
    const float* x    = (const float*)d_in[0];
    const float* u    = (const float*)d_in[1];
    const float* v    = (const float*)d_in[2];
    const float* win  = (const float*)d_in[3];
    const float* wr   = (const float*)d_in[4];
    const float* bias = (const float*)d_in[5];
    float* out = (float*)d_out;

    // 1) convert inputs to bf16 scratch
    const int cb = (int)(TOTAL4 / 256);  // 30720 blocks, exact
    convert_kernel<<<cb, 256>>>((const float4*)x, (const float4*)u,
                                (const float4*)win, (const float4*)wr);

    // 2) fused GEMM + epilogue
    cudaFuncSetAttribute(sfa_rnn_kernel,
                         cudaFuncAttributeMaxDynamicSharedMemorySize, SMEM_TOTAL);
    dim3 grid(H_DIM / BN, B_DIM / BM);  // (8, 64) = 512 CTAs
    sfa_rnn_kernel<<<grid, NTHREADS, SMEM_TOTAL>>>(u, v, bias, out);
}

// round 5
// speedup vs baseline: 1.8450x; 1.0022x over previous
#include <cuda_runtime.h>
#include <cuda_bf16.h>
#include <cstdint>

// Problem dims (fixed by the dataset)
#define B_DIM 8192
#define DIN   1024
#define H_DIM 2048

// Tiling
#define BM 128
#define BN 256
#define BKE 64          // bf16 K-elements per chunk = 128B rows (swizzle atom)
#define NK 48           // 3072 / 64
#define NKX 16          // first 16 chunks: x / win (K=1024)
#define STAGES 3
#define NTHREADS 512    // 16 warps, warp tile 64x32

#define A_BYTES (BM * 128)                 // 16 KB
#define B_BYTES (BN * 128)                 // 32 KB
#define STAGE_BYTES (A_BYTES + B_BYTES)    // 48 KB
#define SMEM_TOTAL (STAGES * STAGE_BYTES)  // 144 KB

// bf16 copies of the inputs (static scratch; no allocation allowed)
__device__ __nv_bfloat16 g_xb[(size_t)B_DIM * DIN];
__device__ __nv_bfloat16 g_ub[(size_t)B_DIM * H_DIM];
__device__ __nv_bfloat16 g_winb[(size_t)H_DIM * DIN];
__device__ __nv_bfloat16 g_wrb[(size_t)H_DIM * H_DIM];

__device__ __forceinline__ uint32_t smem_u32(const void* p) {
    uint32_t a;
    asm("{ .reg .u64 t; cvta.to.shared.u64 t, %1; cvt.u32.u64 %0, t; }"
        : "=r"(a) : "l"(p));
    return a;
}

__device__ __forceinline__ void cp_async16(uint32_t saddr, const void* g) {
    asm volatile("cp.async.cg.shared.global [%0], [%1], 16;\n"
                 :: "r"(saddr), "l"(g));
}

__device__ __forceinline__ void cp_commit() {
    asm volatile("cp.async.commit_group;\n" ::: "memory");
}

template <int N>
__device__ __forceinline__ void cp_wait() {
    asm volatile("cp.async.wait_group %0;\n" :: "n"(N) : "memory");
}

#define LDSM_X4(r, addr) \
    asm volatile("ldmatrix.sync.aligned.m8n8.x4.shared.b16 {%0,%1,%2,%3}, [%4];" \
        : "=r"((r)[0]), "=r"((r)[1]), "=r"((r)[2]), "=r"((r)[3]) : "r"(addr))

__device__ __forceinline__ void mma_bf16(float* c, const uint32_t* a,
                                         uint32_t b0, uint32_t b1) {
    asm volatile(
        "mma.sync.aligned.m16n8k16.row.col.f32.bf16.bf16.f32 "
        "{%0,%1,%2,%3}, {%4,%5,%6,%7}, {%8,%9}, {%0,%1,%2,%3};"
        : "+f"(c[0]), "+f"(c[1]), "+f"(c[2]), "+f"(c[3])
        : "r"(a[0]), "r"(a[1]), "r"(a[2]), "r"(a[3]), "r"(b0), "r"(b1));
}

// ---------------------------------------------------------------------------
// fp32 -> bf16 conversion pre-pass (one float4 per thread)
// ---------------------------------------------------------------------------
#define SX4 ((size_t)B_DIM * DIN / 4)     // 2,097,152
#define SU4 ((size_t)B_DIM * H_DIM / 4)   // 4,194,304
#define SW4 ((size_t)H_DIM * DIN / 4)     //   524,288
#define SR4 ((size_t)H_DIM * H_DIM / 4)   // 1,048,576
#define TOTAL4 (SX4 + SU4 + SW4 + SR4)    // 7,864,320

__global__ void __launch_bounds__(256)
convert_kernel(const float4* __restrict__ x, const float4* __restrict__ u,
               const float4* __restrict__ win, const float4* __restrict__ wr) {
    const size_t i = (size_t)blockIdx.x * blockDim.x + threadIdx.x;
    float4 f;
    __nv_bfloat16* dst;
    size_t j;
    if (i < SX4)                   { j = i;                   f = x[j];   dst = g_xb;   }
    else if (i < SX4 + SU4)        { j = i - SX4;             f = u[j];   dst = g_ub;   }
    else if (i < SX4 + SU4 + SW4)  { j = i - SX4 - SU4;       f = win[j]; dst = g_winb; }
    else if (i < TOTAL4)           { j = i - SX4 - SU4 - SW4; f = wr[j];  dst = g_wrb;  }
    else return;
    __nv_bfloat162* o = reinterpret_cast<__nv_bfloat162*>(dst) + j * 2;
    o[0] = __floats2bfloat162_rn(f.x, f.y);
    o[1] = __floats2bfloat162_rn(f.z, f.w);
}

// ---------------------------------------------------------------------------
// Fused GEMM + SfaRNN epilogue (16 warps, warp tile 64x32)
// ---------------------------------------------------------------------------
__global__ void __launch_bounds__(NTHREADS, 1)
sfa_rnn_kernel(const float* __restrict__ u,
               const float* __restrict__ v,
               const float* __restrict__ bias,
               float* __restrict__ out) {
    extern __shared__ char smem[];
    const uint32_t sbase = smem_u32(smem);

    const int tid  = threadIdx.x;
    const int wid  = tid >> 5;
    const int lane = tid & 31;
    const int lq   = lane >> 2;
    const int lr   = lane & 3;
    const int wm   = wid & 1;    // M half (64 rows)
    const int wn   = wid >> 1;   // N group of 32 cols (0..7)

    const int nb = blockIdx.x * BN;
    const int mb = blockIdx.y * BM;

    // ---------------- producer geometry ----------------
    // 512 threads: each thread 2 x 16B chunks of A + 4 x 16B chunks of B.
    const int rbase = tid >> 3;  // 0..63
    const int c16   = tid & 7;   // 16B chunk within 128B row
    const uint32_t swbase =
        (uint32_t)rbase * 128u + ((uint32_t)(c16 ^ (rbase & 7)) << 4);

    const __nv_bfloat16* gax = g_xb   + (size_t)(mb + rbase) * DIN   + c16 * 8;
    const __nv_bfloat16* gau = g_ub   + (size_t)(mb + rbase) * H_DIM + c16 * 8;
    const __nv_bfloat16* gbw = g_winb + (size_t)(nb + rbase) * DIN   + c16 * 8;
    const __nv_bfloat16* gbr = g_wrb  + (size_t)(nb + rbase) * H_DIM + c16 * 8;

    auto issue_chunk = [&](int k) {
        const int s = k % STAGES;
        const uint32_t sA = sbase + s * STAGE_BYTES;
        const uint32_t sB = sA + A_BYTES;
        if (k < NKX) {
            const __nv_bfloat16* ga = gax + k * BKE;
            const __nv_bfloat16* gb = gbw + k * BKE;
#pragma unroll
            for (int i = 0; i < 2; i++)
                cp_async16(sA + swbase + i * 8192u, ga + (size_t)i * 64 * DIN);
#pragma unroll
            for (int i = 0; i < 4; i++)
                cp_async16(sB + swbase + i * 8192u, gb + (size_t)i * 64 * DIN);
        } else {
            const __nv_bfloat16* ga = gau + (k - NKX) * BKE;
            const __nv_bfloat16* gb = gbr + (k - NKX) * BKE;
#pragma unroll
            for (int i = 0; i < 2; i++)
                cp_async16(sA + swbase + i * 8192u, ga + (size_t)i * 64 * H_DIM);
#pragma unroll
            for (int i = 0; i < 4; i++)
                cp_async16(sB + swbase + i * 8192u, gb + (size_t)i * 64 * H_DIM);
        }
    };

    // ---------------- consumer geometry (ldmatrix) ----------------
    const uint32_t r8   = (uint32_t)(lane & 7);
    const uint32_t a_hi = (uint32_t)(lane >> 4);
    const uint32_t a_m8 = (uint32_t)(((lane >> 3) & 1) << 3);
    const uint32_t b_hi = (uint32_t)((lane >> 3) & 1);
    const uint32_t b_n8 = (uint32_t)((lane >> 4) << 3);

    uint32_t baseA[4];
#pragma unroll
    for (int mi = 0; mi < 4; mi++)
        baseA[mi] = (uint32_t)(wm * 64 + mi * 16) * 128u + (r8 + a_m8) * 128u;
    uint32_t baseB[2];
#pragma unroll
    for (int ni2 = 0; ni2 < 2; ni2++)
        baseB[ni2] = (uint32_t)(wn * 32 + ni2 * 16) * 128u + (r8 + b_n8) * 128u;

    float acc[4][4][4];
#pragma unroll
    for (int mi = 0; mi < 4; mi++)
#pragma unroll
        for (int ni = 0; ni < 4; ni++)
#pragma unroll
            for (int r = 0; r < 4; r++) acc[mi][ni][r] = 0.0f;

    // ---------------- prologue ----------------
    issue_chunk(0); cp_commit();
    issue_chunk(1); cp_commit();

    // ---------------- mainloop (single barrier per chunk) ----------------
#pragma unroll 1
    for (int k = 0; k < NK; k++) {
        cp_wait<1>();
        __syncthreads();
        if (k + 2 < NK) issue_chunk(k + 2);
        cp_commit();

        const int s = k % STAGES;
        const uint32_t sA = sbase + s * STAGE_BYTES;
        const uint32_t sB = sA + A_BYTES;

#pragma unroll
        for (int ks = 0; ks < 4; ks++) {
            const uint32_t offA = (((uint32_t)(2 * ks) + a_hi) ^ r8) << 4;
            const uint32_t offB = (((uint32_t)(2 * ks) + b_hi) ^ r8) << 4;

            uint32_t a[4][4];
#pragma unroll
            for (int mi = 0; mi < 4; mi++) LDSM_X4(a[mi], sA + baseA[mi] + offA);
            uint32_t b[2][4];
#pragma unroll
            for (int ni2 = 0; ni2 < 2; ni2++) LDSM_X4(b[ni2], sB + baseB[ni2] + offB);

#pragma unroll
            for (int mi = 0; mi < 4; mi++)
#pragma unroll
                for (int ni = 0; ni < 4; ni++)
                    mma_bf16(acc[mi][ni], a[mi],
                             b[ni >> 1][(ni & 1) * 2 + 0],
                             b[ni >> 1][(ni & 1) * 2 + 1]);
        }
    }

    // ---------------- fused epilogue ----------------
    const float cu  = 1.0f - (1.0f / 10.0f);
    const float au  = 1.0f / 10.0f;
    const float cv  = 1.0f - (1.0f / 150.0f);
    const float cvm = 10.0f / 150.0f;
    const size_t OUTV = (size_t)B_DIM * H_DIM;

#pragma unroll
    for (int mi = 0; mi < 4; mi++) {
#pragma unroll
        for (int ni = 0; ni < 4; ni++) {
            const int r0 = mb + wm * 64 + mi * 16 + lq;
            const int c  = nb + wn * 32 + ni * 8 + lr * 2;
            const float2 bn = *reinterpret_cast<const float2*>(bias + c);
#pragma unroll
            for (int h = 0; h < 2; h++) {
                const size_t off = (size_t)(r0 + 8 * h) * H_DIM + c;
                const float2 uu = *reinterpret_cast<const float2*>(u + off);
                const float2 vv = *reinterpret_cast<const float2*>(v + off);
                const float g0 = acc[mi][ni][2 * h + 0];
                const float g1 = acc[mi][ni][2 * h + 1];
                const float vn0 = fmaxf(cv * vv.x + cvm * uu.x, 0.0f);
                const float vn1 = fmaxf(cv * vv.y + cvm * uu.y, 0.0f);
                const float un0 = fmaxf(cu * uu.x + au * (g0 + bn.x - vn0), 0.0f);
                const float un1 = fmaxf(cu * uu.y + au * (g1 + bn.y - vn1), 0.0f);
                *reinterpret_cast<float2*>(out + off)        = make_float2(un0, un1);
                *reinterpret_cast<float2*>(out + OUTV + off) = make_float2(vn0, vn1);
            }
        }
    }
}

extern "C" void kernel_launch(void* const* d_in, const int* in_sizes, int n_in,
                              void* d_out, int out_size) {
    (void)in_sizes; (void)n_in; (void)out_size;
    const float* x    = (const float*)d_in[0];
    const float* u    = (const float*)d_in[1];
    const float* v    = (const float*)d_in[2];
    const float* win  = (const float*)d_in[3];
    const float* wr   = (const float*)d_in[4];
    const float* bias = (const float*)d_in[5];
    float* out = (float*)d_out;

    // 1) convert inputs to bf16 scratch
    const int cb = (int)(TOTAL4 / 256);  // 30720 blocks, exact
    convert_kernel<<<cb, 256>>>((const float4*)x, (const float4*)u,
                                (const float4*)win, (const float4*)wr);

    // 2) fused GEMM + epilogue
    cudaFuncSetAttribute(sfa_rnn_kernel,
                         cudaFuncAttributeMaxDynamicSharedMemorySize, SMEM_TOTAL);
    dim3 grid(H_DIM / BN, B_DIM / BM);  // (8, 64) = 512 CTAs
    sfa_rnn_kernel<<<grid, NTHREADS, SMEM_TOTAL>>>(u, v, bias, out);
}

// round 6
// speedup vs baseline: 1.8566x; 1.0063x over previous
#include <cuda_runtime.h>
#include <cuda_bf16.h>
#include <cstdint>

// Problem dims (fixed by the dataset)
#define B_DIM 8192
#define DIN   1024
#define H_DIM 2048

// Tiling
#define BM 128
#define BN 256
#define BKE 64          // bf16 K-elements per chunk = 128B rows (swizzle atom)
#define NK 48           // 3072 / 64
#define NKX 16          // first 16 chunks: x / win (K=1024)
#define STAGES 3
#define NTHREADS 256    // 8 warps, warp tile 64x64

#define A_BYTES (BM * 128)                 // 16 KB
#define B_BYTES (BN * 128)                 // 32 KB
#define STAGE_BYTES (A_BYTES + B_BYTES)    // 48 KB
#define SMEM_TOTAL (STAGES * STAGE_BYTES)  // 144 KB

// bf16 copies of the inputs (static scratch; no allocation allowed)
__device__ __nv_bfloat16 g_xb[(size_t)B_DIM * DIN];
__device__ __nv_bfloat16 g_ub[(size_t)B_DIM * H_DIM];
__device__ __nv_bfloat16 g_winb[(size_t)H_DIM * DIN];
__device__ __nv_bfloat16 g_wrb[(size_t)H_DIM * H_DIM];

__device__ __forceinline__ uint32_t smem_u32(const void* p) {
    uint32_t a;
    asm("{ .reg .u64 t; cvta.to.shared.u64 t, %1; cvt.u32.u64 %0, t; }"
        : "=r"(a) : "l"(p));
    return a;
}

__device__ __forceinline__ void cp_async16(uint32_t saddr, const void* g) {
    asm volatile("cp.async.cg.shared.global [%0], [%1], 16;\n"
                 :: "r"(saddr), "l"(g));
}

__device__ __forceinline__ void cp_commit() {
    asm volatile("cp.async.commit_group;\n" ::: "memory");
}

template <int N>
__device__ __forceinline__ void cp_wait() {
    asm volatile("cp.async.wait_group %0;\n" :: "n"(N) : "memory");
}

#define LDSM_X4(r, addr) \
    asm volatile("ldmatrix.sync.aligned.m8n8.x4.shared.b16 {%0,%1,%2,%3}, [%4];" \
        : "=r"((r)[0]), "=r"((r)[1]), "=r"((r)[2]), "=r"((r)[3]) : "r"(addr))

__device__ __forceinline__ void mma_bf16(float* c, const uint32_t* a,
                                         uint32_t b0, uint32_t b1) {
    asm volatile(
        "mma.sync.aligned.m16n8k16.row.col.f32.bf16.bf16.f32 "
        "{%0,%1,%2,%3}, {%4,%5,%6,%7}, {%8,%9}, {%0,%1,%2,%3};"
        : "+f"(c[0]), "+f"(c[1]), "+f"(c[2]), "+f"(c[3])
        : "r"(a[0]), "r"(a[1]), "r"(a[2]), "r"(a[3]), "r"(b0), "r"(b1));
}

// ---------------------------------------------------------------------------
// fp32 -> bf16 conversion pre-pass (one float4 per thread)
// ---------------------------------------------------------------------------
#define SX4 ((size_t)B_DIM * DIN / 4)     // 2,097,152
#define SU4 ((size_t)B_DIM * H_DIM / 4)   // 4,194,304
#define SW4 ((size_t)H_DIM * DIN / 4)     //   524,288
#define SR4 ((size_t)H_DIM * H_DIM / 4)   // 1,048,576
#define TOTAL4 (SX4 + SU4 + SW4 + SR4)    // 7,864,320

__global__ void __launch_bounds__(256)
convert_kernel(const float4* __restrict__ x, const float4* __restrict__ u,
               const float4* __restrict__ win, const float4* __restrict__ wr) {
    const size_t i = (size_t)blockIdx.x * blockDim.x + threadIdx.x;
    float4 f;
    __nv_bfloat16* dst;
    size_t j;
    if (i < SX4)                   { j = i;                   f = x[j];   dst = g_xb;   }
    else if (i < SX4 + SU4)        { j = i - SX4;             f = u[j];   dst = g_ub;   }
    else if (i < SX4 + SU4 + SW4)  { j = i - SX4 - SU4;       f = win[j]; dst = g_winb; }
    else if (i < TOTAL4)           { j = i - SX4 - SU4 - SW4; f = wr[j];  dst = g_wrb;  }
    else return;
    __nv_bfloat162* o = reinterpret_cast<__nv_bfloat162*>(dst) + j * 2;
    o[0] = __floats2bfloat162_rn(f.x, f.y);
    o[1] = __floats2bfloat162_rn(f.z, f.w);
}

// ---------------------------------------------------------------------------
// Fused GEMM + SfaRNN epilogue (8 warps, 64x64, double-buffered fragments)
// ---------------------------------------------------------------------------
__global__ void __launch_bounds__(NTHREADS, 1)
sfa_rnn_kernel(const float* __restrict__ u,
               const float* __restrict__ v,
               const float* __restrict__ bias,
               float* __restrict__ out) {
    extern __shared__ char smem[];
    const uint32_t sbase = smem_u32(smem);

    const int tid  = threadIdx.x;
    const int wid  = tid >> 5;
    const int lane = tid & 31;
    const int lq   = lane >> 2;
    const int lr   = lane & 3;
    const int wm   = wid & 1;    // M half (64 rows)
    const int wn   = wid >> 1;   // N quarter (64 cols)

    const int nb = blockIdx.x * BN;
    const int mb = blockIdx.y * BM;

    // ---------------- producer geometry ----------------
    const int rbase = tid >> 3;  // 0..31
    const int c16   = tid & 7;   // 16B chunk within 128B row
    const uint32_t swbase =
        (uint32_t)rbase * 128u + ((uint32_t)(c16 ^ (rbase & 7)) << 4);

    const __nv_bfloat16* gax = g_xb   + (size_t)(mb + rbase) * DIN   + c16 * 8;
    const __nv_bfloat16* gau = g_ub   + (size_t)(mb + rbase) * H_DIM + c16 * 8;
    const __nv_bfloat16* gbw = g_winb + (size_t)(nb + rbase) * DIN   + c16 * 8;
    const __nv_bfloat16* gbr = g_wrb  + (size_t)(nb + rbase) * H_DIM + c16 * 8;

    auto issue_chunk = [&](int k) {
        const int s = k % STAGES;
        const uint32_t sA = sbase + s * STAGE_BYTES;
        const uint32_t sB = sA + A_BYTES;
        if (k < NKX) {
            const __nv_bfloat16* ga = gax + k * BKE;
            const __nv_bfloat16* gb = gbw + k * BKE;
#pragma unroll
            for (int i = 0; i < 4; i++)
                cp_async16(sA + swbase + i * 4096u, ga + (size_t)i * 32 * DIN);
#pragma unroll
            for (int i = 0; i < 8; i++)
                cp_async16(sB + swbase + i * 4096u, gb + (size_t)i * 32 * DIN);
        } else {
            const __nv_bfloat16* ga = gau + (k - NKX) * BKE;
            const __nv_bfloat16* gb = gbr + (k - NKX) * BKE;
#pragma unroll
            for (int i = 0; i < 4; i++)
                cp_async16(sA + swbase + i * 4096u, ga + (size_t)i * 32 * H_DIM);
#pragma unroll
            for (int i = 0; i < 8; i++)
                cp_async16(sB + swbase + i * 4096u, gb + (size_t)i * 32 * H_DIM);
        }
    };

    // ---------------- consumer geometry (ldmatrix) ----------------
    const uint32_t r8   = (uint32_t)(lane & 7);
    const uint32_t a_hi = (uint32_t)(lane >> 4);
    const uint32_t a_m8 = (uint32_t)(((lane >> 3) & 1) << 3);
    const uint32_t b_hi = (uint32_t)((lane >> 3) & 1);
    const uint32_t b_n8 = (uint32_t)((lane >> 4) << 3);

    uint32_t baseA[4];
#pragma unroll
    for (int mi = 0; mi < 4; mi++)
        baseA[mi] = (uint32_t)(wm * 64 + mi * 16) * 128u + (r8 + a_m8) * 128u;
    uint32_t baseB[4];
#pragma unroll
    for (int ni2 = 0; ni2 < 4; ni2++)
        baseB[ni2] = (uint32_t)(wn * 64 + ni2 * 16) * 128u + (r8 + b_n8) * 128u;

    float acc[4][8][4];
#pragma unroll
    for (int mi = 0; mi < 4; mi++)
#pragma unroll
        for (int ni = 0; ni < 8; ni++)
#pragma unroll
            for (int r = 0; r < 4; r++) acc[mi][ni][r] = 0.0f;

    // double-buffered fragments
    uint32_t a[2][4][4];
    uint32_t b[2][4][4];

    // ---------------- prologue ----------------
    issue_chunk(0); cp_commit();
    issue_chunk(1); cp_commit();

    // ---------------- mainloop ----------------
#pragma unroll 1
    for (int k = 0; k < NK; k++) {
        cp_wait<1>();
        __syncthreads();
        if (k + 2 < NK) issue_chunk(k + 2);
        cp_commit();

        const int s = k % STAGES;
        const uint32_t sA = sbase + s * STAGE_BYTES;
        const uint32_t sB = sA + A_BYTES;

        // load fragments for ks=0 into buffer 0
        {
            const uint32_t offA = (a_hi ^ r8) << 4;
            const uint32_t offB = (b_hi ^ r8) << 4;
#pragma unroll
            for (int mi = 0; mi < 4; mi++) LDSM_X4(a[0][mi], sA + baseA[mi] + offA);
#pragma unroll
            for (int ni2 = 0; ni2 < 4; ni2++) LDSM_X4(b[0][ni2], sB + baseB[ni2] + offB);
        }

#pragma unroll
        for (int ks = 0; ks < 4; ks++) {
            const int cur = ks & 1;
            const int nxt = cur ^ 1;
            if (ks < 3) {
                // prefetch ks+1 fragments BEFORE this step's MMA burst
                const uint32_t offA = (((uint32_t)(2 * (ks + 1)) + a_hi) ^ r8) << 4;
                const uint32_t offB = (((uint32_t)(2 * (ks + 1)) + b_hi) ^ r8) << 4;
#pragma unroll
                for (int mi = 0; mi < 4; mi++)
                    LDSM_X4(a[nxt][mi], sA + baseA[mi] + offA);
#pragma unroll
                for (int ni2 = 0; ni2 < 4; ni2++)
                    LDSM_X4(b[nxt][ni2], sB + baseB[ni2] + offB);
            }
#pragma unroll
            for (int mi = 0; mi < 4; mi++)
#pragma unroll
                for (int ni = 0; ni < 8; ni++)
                    mma_bf16(acc[mi][ni], a[cur][mi],
                             b[cur][ni >> 1][(ni & 1) * 2 + 0],
                             b[cur][ni >> 1][(ni & 1) * 2 + 1]);
        }
    }

    // ---------------- fused epilogue ----------------
    const float cu  = 1.0f - (1.0f / 10.0f);
    const float au  = 1.0f / 10.0f;
    const float cv  = 1.0f - (1.0f / 150.0f);
    const float cvm = 10.0f / 150.0f;
    const size_t OUTV = (size_t)B_DIM * H_DIM;

#pragma unroll
    for (int mi = 0; mi < 4; mi++) {
#pragma unroll
        for (int ni = 0; ni < 8; ni++) {
            const int r0 = mb + wm * 64 + mi * 16 + lq;
            const int c  = nb + wn * 64 + ni * 8 + lr * 2;
            const float2 bn = *reinterpret_cast<const float2*>(bias + c);
#pragma unroll
            for (int h = 0; h < 2; h++) {
                const size_t off = (size_t)(r0 + 8 * h) * H_DIM + c;
                const float2 uu = *reinterpret_cast<const float2*>(u + off);
                const float2 vv = *reinterpret_cast<const float2*>(v + off);
                const float g0 = acc[mi][ni][2 * h + 0];
                const float g1 = acc[mi][ni][2 * h + 1];
                const float vn0 = fmaxf(cv * vv.x + cvm * uu.x, 0.0f);
                const float vn1 = fmaxf(cv * vv.y + cvm * uu.y, 0.0f);
                const float un0 = fmaxf(cu * uu.x + au * (g0 + bn.x - vn0), 0.0f);
                const float un1 = fmaxf(cu * uu.y + au * (g1 + bn.y - vn1), 0.0f);
                *reinterpret_cast<float2*>(out + off)        = make_float2(un0, un1);
                *reinterpret_cast<float2*>(out + OUTV + off) = make_float2(vn0, vn1);
            }
        }
    }
}

extern "C" void kernel_launch(void* const* d_in, const int* in_sizes, int n_in,
                              void* d_out, int out_size) {
    (void)in_sizes; (void)n_in; (void)out_size;
    const float* x    = (const float*)d_in[0];
    const float* u    = (const float*)d_in[1];
    const float* v    = (const float*)d_in[2];
    const float* win  = (const float*)d_in[3];
    const float* wr   = (const float*)d_in[4];
    const float* bias = (const float*)d_in[5];
    float* out = (float*)d_out;

    // 1) convert inputs to bf16 scratch
    const int cb = (int)(TOTAL4 / 256);  // 30720 blocks, exact
    convert_kernel<<<cb, 256>>>((const float4*)x, (const float4*)u,
                                (const float4*)win, (const float4*)wr);

    // 2) fused GEMM + epilogue
    cudaFuncSetAttribute(sfa_rnn_kernel,
                         cudaFuncAttributeMaxDynamicSharedMemorySize, SMEM_TOTAL);
    dim3 grid(H_DIM / BN, B_DIM / BM);  // (8, 64) = 512 CTAs
    sfa_rnn_kernel<<<grid, NTHREADS, SMEM_TOTAL>>>(u, v, bias, out);
}

// round 7
// speedup vs baseline: 1.8730x; 1.0088x over previous
#include <cuda_runtime.h>
#include <cuda_bf16.h>
#include <cstdint>

// Problem dims (fixed by the dataset)
#define B_DIM 8192
#define DIN   1024
#define H_DIM 2048

// Tiling
#define BM 128
#define BN 256
#define BKE 64          // bf16 K-elements per chunk = 128B rows (swizzle atom)
#define NK 48           // 3072 / 64
#define NKX 16          // first 16 chunks: x / win (K=1024)
#define STAGES 4
#define NTHREADS 256    // 8 warps, warp tile 64x64

#define A_BYTES (BM * 128)                 // 16 KB
#define B_BYTES (BN * 128)                 // 32 KB
#define STAGE_BYTES (A_BYTES + B_BYTES)    // 48 KB
#define SMEM_TOTAL (STAGES * STAGE_BYTES)  // 192 KB

// bf16 copies of the inputs (static scratch; no allocation allowed)
__device__ __nv_bfloat16 g_xb[(size_t)B_DIM * DIN];
__device__ __nv_bfloat16 g_ub[(size_t)B_DIM * H_DIM];
__device__ __nv_bfloat16 g_winb[(size_t)H_DIM * DIN];
__device__ __nv_bfloat16 g_wrb[(size_t)H_DIM * H_DIM];

__device__ __forceinline__ uint32_t smem_u32(const void* p) {
    uint32_t a;
    asm("{ .reg .u64 t; cvta.to.shared.u64 t, %1; cvt.u32.u64 %0, t; }"
        : "=r"(a) : "l"(p));
    return a;
}

__device__ __forceinline__ void cp_async16(uint32_t saddr, const void* g) {
    asm volatile("cp.async.cg.shared.global [%0], [%1], 16;\n"
                 :: "r"(saddr), "l"(g));
}

__device__ __forceinline__ void cp_commit() {
    asm volatile("cp.async.commit_group;\n" ::: "memory");
}

template <int N>
__device__ __forceinline__ void cp_wait() {
    asm volatile("cp.async.wait_group %0;\n" :: "n"(N) : "memory");
}

#define LDSM_X4(r, addr) \
    asm volatile("ldmatrix.sync.aligned.m8n8.x4.shared.b16 {%0,%1,%2,%3}, [%4];" \
        : "=r"((r)[0]), "=r"((r)[1]), "=r"((r)[2]), "=r"((r)[3]) : "r"(addr))

__device__ __forceinline__ void mma_bf16(float* c, const uint32_t* a,
                                         uint32_t b0, uint32_t b1) {
    asm volatile(
        "mma.sync.aligned.m16n8k16.row.col.f32.bf16.bf16.f32 "
        "{%0,%1,%2,%3}, {%4,%5,%6,%7}, {%8,%9}, {%0,%1,%2,%3};"
        : "+f"(c[0]), "+f"(c[1]), "+f"(c[2]), "+f"(c[3])
        : "r"(a[0]), "r"(a[1]), "r"(a[2]), "r"(a[3]), "r"(b0), "r"(b1));
}

// ---------------------------------------------------------------------------
// fp32 -> bf16 conversion pre-pass (one float4 per thread)
// ---------------------------------------------------------------------------
#define SX4 ((size_t)B_DIM * DIN / 4)     // 2,097,152
#define SU4 ((size_t)B_DIM * H_DIM / 4)   // 4,194,304
#define SW4 ((size_t)H_DIM * DIN / 4)     //   524,288
#define SR4 ((size_t)H_DIM * H_DIM / 4)   // 1,048,576
#define TOTAL4 (SX4 + SU4 + SW4 + SR4)    // 7,864,320

__global__ void __launch_bounds__(256)
convert_kernel(const float4* __restrict__ x, const float4* __restrict__ u,
               const float4* __restrict__ win, const float4* __restrict__ wr) {
    const size_t i = (size_t)blockIdx.x * blockDim.x + threadIdx.x;
    float4 f;
    __nv_bfloat16* dst;
    size_t j;
    if (i < SX4)                   { j = i;                   f = x[j];   dst = g_xb;   }
    else if (i < SX4 + SU4)        { j = i - SX4;             f = u[j];   dst = g_ub;   }
    else if (i < SX4 + SU4 + SW4)  { j = i - SX4 - SU4;       f = win[j]; dst = g_winb; }
    else if (i < TOTAL4)           { j = i - SX4 - SU4 - SW4; f = wr[j];  dst = g_wrb;  }
    else return;
    __nv_bfloat162* o = reinterpret_cast<__nv_bfloat162*>(dst) + j * 2;
    o[0] = __floats2bfloat162_rn(f.x, f.y);
    o[1] = __floats2bfloat162_rn(f.z, f.w);
}

// ---------------------------------------------------------------------------
// Fused GEMM + SfaRNN epilogue (8 warps, 64x64, 4-stage deep pipeline)
// ---------------------------------------------------------------------------
__global__ void __launch_bounds__(NTHREADS, 1)
sfa_rnn_kernel(const float* __restrict__ u,
               const float* __restrict__ v,
               const float* __restrict__ bias,
               float* __restrict__ out) {
    extern __shared__ char smem[];
    const uint32_t sbase = smem_u32(smem);

    const int tid  = threadIdx.x;
    const int wid  = tid >> 5;
    const int lane = tid & 31;
    const int lq   = lane >> 2;
    const int lr   = lane & 3;
    const int wm   = wid & 1;    // M half (64 rows)
    const int wn   = wid >> 1;   // N quarter (64 cols)

    const int nb = blockIdx.x * BN;
    const int mb = blockIdx.y * BM;

    // ---------------- producer geometry ----------------
    const int rbase = tid >> 3;  // 0..31
    const int c16   = tid & 7;   // 16B chunk within 128B row
    const uint32_t swbase =
        (uint32_t)rbase * 128u + ((uint32_t)(c16 ^ (rbase & 7)) << 4);

    const __nv_bfloat16* gax = g_xb   + (size_t)(mb + rbase) * DIN   + c16 * 8;
    const __nv_bfloat16* gau = g_ub   + (size_t)(mb + rbase) * H_DIM + c16 * 8;
    const __nv_bfloat16* gbw = g_winb + (size_t)(nb + rbase) * DIN   + c16 * 8;
    const __nv_bfloat16* gbr = g_wrb  + (size_t)(nb + rbase) * H_DIM + c16 * 8;

    auto issue_chunk = [&](int k) {
        const int s = k % STAGES;
        const uint32_t sA = sbase + s * STAGE_BYTES;
        const uint32_t sB = sA + A_BYTES;
        if (k < NKX) {
            const __nv_bfloat16* ga = gax + k * BKE;
            const __nv_bfloat16* gb = gbw + k * BKE;
#pragma unroll
            for (int i = 0; i < 4; i++)
                cp_async16(sA + swbase + i * 4096u, ga + (size_t)i * 32 * DIN);
#pragma unroll
            for (int i = 0; i < 8; i++)
                cp_async16(sB + swbase + i * 4096u, gb + (size_t)i * 32 * DIN);
        } else {
            const __nv_bfloat16* ga = gau + (k - NKX) * BKE;
            const __nv_bfloat16* gb = gbr + (k - NKX) * BKE;
#pragma unroll
            for (int i = 0; i < 4; i++)
                cp_async16(sA + swbase + i * 4096u, ga + (size_t)i * 32 * H_DIM);
#pragma unroll
            for (int i = 0; i < 8; i++)
                cp_async16(sB + swbase + i * 4096u, gb + (size_t)i * 32 * H_DIM);
        }
    };

    // ---------------- consumer geometry (ldmatrix) ----------------
    const uint32_t r8   = (uint32_t)(lane & 7);
    const uint32_t a_hi = (uint32_t)(lane >> 4);
    const uint32_t a_m8 = (uint32_t)(((lane >> 3) & 1) << 3);
    const uint32_t b_hi = (uint32_t)((lane >> 3) & 1);
    const uint32_t b_n8 = (uint32_t)((lane >> 4) << 3);

    uint32_t baseA[4];
#pragma unroll
    for (int mi = 0; mi < 4; mi++)
        baseA[mi] = (uint32_t)(wm * 64 + mi * 16) * 128u + (r8 + a_m8) * 128u;
    uint32_t baseB[4];
#pragma unroll
    for (int ni2 = 0; ni2 < 4; ni2++)
        baseB[ni2] = (uint32_t)(wn * 64 + ni2 * 16) * 128u + (r8 + b_n8) * 128u;

    float acc[4][8][4];
#pragma unroll
    for (int mi = 0; mi < 4; mi++)
#pragma unroll
        for (int ni = 0; ni < 8; ni++)
#pragma unroll
            for (int r = 0; r < 4; r++) acc[mi][ni][r] = 0.0f;

    // ---------------- prologue: 3 chunks in flight ----------------
    issue_chunk(0); cp_commit();
    issue_chunk(1); cp_commit();
    issue_chunk(2); cp_commit();

    // ---------------- mainloop ----------------
#pragma unroll 1
    for (int k = 0; k < NK; k++) {
        cp_wait<2>();       // chunk k has landed; k+1, k+2 may be pending
        __syncthreads();    // k visible to all; all warps done computing k-1

        // refill the slot vacated by chunk k-1 with chunk k+3
        if (k + 3 < NK) { issue_chunk(k + 3); }
        cp_commit();

        const int s = k % STAGES;
        const uint32_t sA = sbase + s * STAGE_BYTES;
        const uint32_t sB = sA + A_BYTES;

#pragma unroll
        for (int ks = 0; ks < 4; ks++) {
            const uint32_t offA = (((uint32_t)(2 * ks) + a_hi) ^ r8) << 4;
            const uint32_t offB = (((uint32_t)(2 * ks) + b_hi) ^ r8) << 4;

            uint32_t a[4][4];
#pragma unroll
            for (int mi = 0; mi < 4; mi++) LDSM_X4(a[mi], sA + baseA[mi] + offA);
            uint32_t b[4][4];
#pragma unroll
            for (int ni2 = 0; ni2 < 4; ni2++) LDSM_X4(b[ni2], sB + baseB[ni2] + offB);

#pragma unroll
            for (int mi = 0; mi < 4; mi++)
#pragma unroll
                for (int ni = 0; ni < 8; ni++)
                    mma_bf16(acc[mi][ni], a[mi],
                             b[ni >> 1][(ni & 1) * 2 + 0],
                             b[ni >> 1][(ni & 1) * 2 + 1]);
        }
    }

    // ---------------- fused epilogue ----------------
    const float cu  = 1.0f - (1.0f / 10.0f);
    const float au  = 1.0f / 10.0f;
    const float cv  = 1.0f - (1.0f / 150.0f);
    const float cvm = 10.0f / 150.0f;
    const size_t OUTV = (size_t)B_DIM * H_DIM;

#pragma unroll
    for (int mi = 0; mi < 4; mi++) {
#pragma unroll
        for (int ni = 0; ni < 8; ni++) {
            const int r0 = mb + wm * 64 + mi * 16 + lq;
            const int c  = nb + wn * 64 + ni * 8 + lr * 2;
            const float2 bn = *reinterpret_cast<const float2*>(bias + c);
#pragma unroll
            for (int h = 0; h < 2; h++) {
                const size_t off = (size_t)(r0 + 8 * h) * H_DIM + c;
                const float2 uu = *reinterpret_cast<const float2*>(u + off);
                const float2 vv = *reinterpret_cast<const float2*>(v + off);
                const float g0 = acc[mi][ni][2 * h + 0];
                const float g1 = acc[mi][ni][2 * h + 1];
                const float vn0 = fmaxf(cv * vv.x + cvm * uu.x, 0.0f);
                const float vn1 = fmaxf(cv * vv.y + cvm * uu.y, 0.0f);
                const float un0 = fmaxf(cu * uu.x + au * (g0 + bn.x - vn0), 0.0f);
                const float un1 = fmaxf(cu * uu.y + au * (g1 + bn.y - vn1), 0.0f);
                *reinterpret_cast<float2*>(out + off)        = make_float2(un0, un1);
                *reinterpret_cast<float2*>(out + OUTV + off) = make_float2(vn0, vn1);
            }
        }
    }
}

extern "C" void kernel_launch(void* const* d_in, const int* in_sizes, int n_in,
                              void* d_out, int out_size) {
    (void)in_sizes; (void)n_in; (void)out_size;
    const float* x    = (const float*)d_in[0];
    const float* u    = (const float*)d_in[1];
    const float* v    = (const float*)d_in[2];
    const float* win  = (const float*)d_in[3];
    const float* wr   = (const float*)d_in[4];
    const float* bias = (const float*)d_in[5];
    float* out = (float*)d_out;

    // 1) convert inputs to bf16 scratch
    const int cb = (int)(TOTAL4 / 256);  // 30720 blocks, exact
    convert_kernel<<<cb, 256>>>((const float4*)x, (const float4*)u,
                                (const float4*)win, (const float4*)wr);

    // 2) fused GEMM + epilogue
    cudaFuncSetAttribute(sfa_rnn_kernel,
                         cudaFuncAttributeMaxDynamicSharedMemorySize, SMEM_TOTAL);
    dim3 grid(H_DIM / BN, B_DIM / BM);  // (8, 64) = 512 CTAs
    sfa_rnn_kernel<<<grid, NTHREADS, SMEM_TOTAL>>>(u, v, bias, out);
}

// round 8
// speedup vs baseline: 2.2408x; 1.1964x over previous
#include <cuda_runtime.h>
#include <cuda_bf16.h>
#include <cstdint>

// Problem dims (fixed by the dataset)
#define B_DIM 8192
#define DIN   1024
#define H_DIM 2048

// Tiling: 128x128 CTA tile, 2 CTAs per SM for phase-decoupled overlap
#define BM 128
#define BN 128
#define BKE 64          // bf16 K-elements per chunk = 128B rows (swizzle atom)
#define NK 48           // 3072 / 64
#define NKX 16          // first 16 chunks: x / win (K=1024)
#define STAGES 3
#define NTHREADS 256    // 8 warps, warp tile 64x32

#define A_BYTES (BM * 128)                 // 16 KB
#define B_BYTES (BN * 128)                 // 16 KB
#define STAGE_BYTES (A_BYTES + B_BYTES)    // 32 KB
#define SMEM_TOTAL (STAGES * STAGE_BYTES)  // 96 KB  (x2 CTAs = 192 KB/SM)

// bf16 copies of the inputs (static scratch; no allocation allowed)
__device__ __nv_bfloat16 g_xb[(size_t)B_DIM * DIN];
__device__ __nv_bfloat16 g_ub[(size_t)B_DIM * H_DIM];
__device__ __nv_bfloat16 g_winb[(size_t)H_DIM * DIN];
__device__ __nv_bfloat16 g_wrb[(size_t)H_DIM * H_DIM];

__device__ __forceinline__ uint32_t smem_u32(const void* p) {
    uint32_t a;
    asm("{ .reg .u64 t; cvta.to.shared.u64 t, %1; cvt.u32.u64 %0, t; }"
        : "=r"(a) : "l"(p));
    return a;
}

__device__ __forceinline__ void cp_async16(uint32_t saddr, const void* g) {
    asm volatile("cp.async.cg.shared.global [%0], [%1], 16;\n"
                 :: "r"(saddr), "l"(g));
}

__device__ __forceinline__ void cp_commit() {
    asm volatile("cp.async.commit_group;\n" ::: "memory");
}

template <int N>
__device__ __forceinline__ void cp_wait() {
    asm volatile("cp.async.wait_group %0;\n" :: "n"(N) : "memory");
}

#define LDSM_X4(r, addr) \
    asm volatile("ldmatrix.sync.aligned.m8n8.x4.shared.b16 {%0,%1,%2,%3}, [%4];" \
        : "=r"((r)[0]), "=r"((r)[1]), "=r"((r)[2]), "=r"((r)[3]) : "r"(addr))

__device__ __forceinline__ void mma_bf16(float* c, const uint32_t* a,
                                         uint32_t b0, uint32_t b1) {
    asm volatile(
        "mma.sync.aligned.m16n8k16.row.col.f32.bf16.bf16.f32 "
        "{%0,%1,%2,%3}, {%4,%5,%6,%7}, {%8,%9}, {%0,%1,%2,%3};"
        : "+f"(c[0]), "+f"(c[1]), "+f"(c[2]), "+f"(c[3])
        : "r"(a[0]), "r"(a[1]), "r"(a[2]), "r"(a[3]), "r"(b0), "r"(b1));
}

// ---------------------------------------------------------------------------
// fp32 -> bf16 conversion pre-pass (one float4 per thread)
// ---------------------------------------------------------------------------
#define SX4 ((size_t)B_DIM * DIN / 4)     // 2,097,152
#define SU4 ((size_t)B_DIM * H_DIM / 4)   // 4,194,304
#define SW4 ((size_t)H_DIM * DIN / 4)     //   524,288
#define SR4 ((size_t)H_DIM * H_DIM / 4)   // 1,048,576
#define TOTAL4 (SX4 + SU4 + SW4 + SR4)    // 7,864,320

__global__ void __launch_bounds__(256)
convert_kernel(const float4* __restrict__ x, const float4* __restrict__ u,
               const float4* __restrict__ win, const float4* __restrict__ wr) {
    const size_t i = (size_t)blockIdx.x * blockDim.x + threadIdx.x;
    float4 f;
    __nv_bfloat16* dst;
    size_t j;
    if (i < SX4)                   { j = i;                   f = x[j];   dst = g_xb;   }
    else if (i < SX4 + SU4)        { j = i - SX4;             f = u[j];   dst = g_ub;   }
    else if (i < SX4 + SU4 + SW4)  { j = i - SX4 - SU4;       f = win[j]; dst = g_winb; }
    else if (i < TOTAL4)           { j = i - SX4 - SU4 - SW4; f = wr[j];  dst = g_wrb;  }
    else return;
    __nv_bfloat162* o = reinterpret_cast<__nv_bfloat162*>(dst) + j * 2;
    o[0] = __floats2bfloat162_rn(f.x, f.y);
    o[1] = __floats2bfloat162_rn(f.z, f.w);
}

// ---------------------------------------------------------------------------
// Fused GEMM + SfaRNN epilogue (128x128 tile, 2 CTAs/SM)
// ---------------------------------------------------------------------------
__global__ void __launch_bounds__(NTHREADS, 2)
sfa_rnn_kernel(const float* __restrict__ u,
               const float* __restrict__ v,
               const float* __restrict__ bias,
               float* __restrict__ out) {
    extern __shared__ char smem[];
    const uint32_t sbase = smem_u32(smem);

    const int tid  = threadIdx.x;
    const int wid  = tid >> 5;
    const int lane = tid & 31;
    const int lq   = lane >> 2;
    const int lr   = lane & 3;
    const int wm   = wid & 1;    // M half (64 rows)
    const int wn   = wid >> 1;   // N group of 32 cols (0..3)

    const int nb = blockIdx.x * BN;
    const int mb = blockIdx.y * BM;

    // ---------------- producer geometry ----------------
    // Per chunk: A 16KB + B 16KB = 2048 x 16B; 256 threads -> 8 each (4 A + 4 B)
    const int rbase = tid >> 3;  // 0..31
    const int c16   = tid & 7;   // 16B chunk within 128B row
    const uint32_t swbase =
        (uint32_t)rbase * 128u + ((uint32_t)(c16 ^ (rbase & 7)) << 4);

    const __nv_bfloat16* gax = g_xb   + (size_t)(mb + rbase) * DIN   + c16 * 8;
    const __nv_bfloat16* gau = g_ub   + (size_t)(mb + rbase) * H_DIM + c16 * 8;
    const __nv_bfloat16* gbw = g_winb + (size_t)(nb + rbase) * DIN   + c16 * 8;
    const __nv_bfloat16* gbr = g_wrb  + (size_t)(nb + rbase) * H_DIM + c16 * 8;

    auto issue_chunk = [&](int k) {
        const int s = k % STAGES;
        const uint32_t sA = sbase + s * STAGE_BYTES;
        const uint32_t sB = sA + A_BYTES;
        if (k < NKX) {
            const __nv_bfloat16* ga = gax + k * BKE;
            const __nv_bfloat16* gb = gbw + k * BKE;
#pragma unroll
            for (int i = 0; i < 4; i++)
                cp_async16(sA + swbase + i * 4096u, ga + (size_t)i * 32 * DIN);
#pragma unroll
            for (int i = 0; i < 4; i++)
                cp_async16(sB + swbase + i * 4096u, gb + (size_t)i * 32 * DIN);
        } else {
            const __nv_bfloat16* ga = gau + (k - NKX) * BKE;
            const __nv_bfloat16* gb = gbr + (k - NKX) * BKE;
#pragma unroll
            for (int i = 0; i < 4; i++)
                cp_async16(sA + swbase + i * 4096u, ga + (size_t)i * 32 * H_DIM);
#pragma unroll
            for (int i = 0; i < 4; i++)
                cp_async16(sB + swbase + i * 4096u, gb + (size_t)i * 32 * H_DIM);
        }
    };

    // ---------------- consumer geometry (ldmatrix) ----------------
    const uint32_t r8   = (uint32_t)(lane & 7);
    const uint32_t a_hi = (uint32_t)(lane >> 4);
    const uint32_t a_m8 = (uint32_t)(((lane >> 3) & 1) << 3);
    const uint32_t b_hi = (uint32_t)((lane >> 3) & 1);
    const uint32_t b_n8 = (uint32_t)((lane >> 4) << 3);

    uint32_t baseA[4];
#pragma unroll
    for (int mi = 0; mi < 4; mi++)
        baseA[mi] = (uint32_t)(wm * 64 + mi * 16) * 128u + (r8 + a_m8) * 128u;
    uint32_t baseB[2];
#pragma unroll
    for (int ni2 = 0; ni2 < 2; ni2++)
        baseB[ni2] = (uint32_t)(wn * 32 + ni2 * 16) * 128u + (r8 + b_n8) * 128u;

    float acc[4][4][4];
#pragma unroll
    for (int mi = 0; mi < 4; mi++)
#pragma unroll
        for (int ni = 0; ni < 4; ni++)
#pragma unroll
            for (int r = 0; r < 4; r++) acc[mi][ni][r] = 0.0f;

    // ---------------- prologue ----------------
    issue_chunk(0); cp_commit();
    issue_chunk(1); cp_commit();

    // ---------------- mainloop ----------------
#pragma unroll 1
    for (int k = 0; k < NK; k++) {
        cp_wait<1>();
        __syncthreads();
        if (k + 2 < NK) issue_chunk(k + 2);
        cp_commit();

        const int s = k % STAGES;
        const uint32_t sA = sbase + s * STAGE_BYTES;
        const uint32_t sB = sA + A_BYTES;

#pragma unroll
        for (int ks = 0; ks < 4; ks++) {
            const uint32_t offA = (((uint32_t)(2 * ks) + a_hi) ^ r8) << 4;
            const uint32_t offB = (((uint32_t)(2 * ks) + b_hi) ^ r8) << 4;

            uint32_t a[4][4];
#pragma unroll
            for (int mi = 0; mi < 4; mi++) LDSM_X4(a[mi], sA + baseA[mi] + offA);
            uint32_t b[2][4];
#pragma unroll
            for (int ni2 = 0; ni2 < 2; ni2++) LDSM_X4(b[ni2], sB + baseB[ni2] + offB);

#pragma unroll
            for (int mi = 0; mi < 4; mi++)
#pragma unroll
                for (int ni = 0; ni < 4; ni++)
                    mma_bf16(acc[mi][ni], a[mi],
                             b[ni >> 1][(ni & 1) * 2 + 0],
                             b[ni >> 1][(ni & 1) * 2 + 1]);
        }
    }

    // ---------------- fused epilogue ----------------
    const float cu  = 1.0f - (1.0f / 10.0f);
    const float au  = 1.0f / 10.0f;
    const float cv  = 1.0f - (1.0f / 150.0f);
    const float cvm = 10.0f / 150.0f;
    const size_t OUTV = (size_t)B_DIM * H_DIM;

#pragma unroll
    for (int mi = 0; mi < 4; mi++) {
#pragma unroll
        for (int ni = 0; ni < 4; ni++) {
            const int r0 = mb + wm * 64 + mi * 16 + lq;
            const int c  = nb + wn * 32 + ni * 8 + lr * 2;
            const float2 bn = *reinterpret_cast<const float2*>(bias + c);
#pragma unroll
            for (int h = 0; h < 2; h++) {
                const size_t off = (size_t)(r0 + 8 * h) * H_DIM + c;
                const float2 uu = *reinterpret_cast<const float2*>(u + off);
                const float2 vv = *reinterpret_cast<const float2*>(v + off);
                const float g0 = acc[mi][ni][2 * h + 0];
                const float g1 = acc[mi][ni][2 * h + 1];
                const float vn0 = fmaxf(cv * vv.x + cvm * uu.x, 0.0f);
                const float vn1 = fmaxf(cv * vv.y + cvm * uu.y, 0.0f);
                const float un0 = fmaxf(cu * uu.x + au * (g0 + bn.x - vn0), 0.0f);
                const float un1 = fmaxf(cu * uu.y + au * (g1 + bn.y - vn1), 0.0f);
                *reinterpret_cast<float2*>(out + off)        = make_float2(un0, un1);
                *reinterpret_cast<float2*>(out + OUTV + off) = make_float2(vn0, vn1);
            }
        }
    }
}

extern "C" void kernel_launch(void* const* d_in, const int* in_sizes, int n_in,
                              void* d_out, int out_size) {
    (void)in_sizes; (void)n_in; (void)out_size;
    const float* x    = (const float*)d_in[0];
    const float* u    = (const float*)d_in[1];
    const float* v    = (const float*)d_in[2];
    const float* win  = (const float*)d_in[3];
    const float* wr   = (const float*)d_in[4];
    const float* bias = (const float*)d_in[5];
    float* out = (float*)d_out;

    // 1) convert inputs to bf16 scratch
    const int cb = (int)(TOTAL4 / 256);  // 30720 blocks, exact
    convert_kernel<<<cb, 256>>>((const float4*)x, (const float4*)u,
                                (const float4*)win, (const float4*)wr);

    // 2) fused GEMM + epilogue
    cudaFuncSetAttribute(sfa_rnn_kernel,
                         cudaFuncAttributeMaxDynamicSharedMemorySize, SMEM_TOTAL);
    dim3 grid(H_DIM / BN, B_DIM / BM);  // (16, 64) = 1024 CTAs
    sfa_rnn_kernel<<<grid, NTHREADS, SMEM_TOTAL>>>(u, v, bias, out);
}